// round 1
// baseline (speedup 1.0000x reference)
#include <cuda_runtime.h>
#include <cuda_bf16.h>
#include <math.h>
#include <stdint.h>

// Problem dims (fixed)
#define L_   1024
#define D_   512
#define E_   4
#define V_   32000
#define R_   (L_*E_)     // 4096 rows of the decoder GEMM
#define ED_  (E_*D_)     // 2048

// ------------------------- device scratch -------------------------
__device__ __nv_bfloat16 g_h_bf[L_*D_];        // hidden_states bf16
__device__ __nv_bfloat16 g_Wlat_bf[D_*ED_];    // W_latent bf16
__device__ __nv_bfloat16 g_Wdec_bf[D_*V_];     // W_dec bf16
__device__ __nv_bfloat16 g_latent[R_*D_];      // tanh latent, row r = l*4+e
__device__ float         g_logits[(size_t)R_*V_];  // 524 MB scratch
__device__ float         g_logcoef[R_];        // log softmax of prior logits
__device__ float         g_rowsum[R_];         // sum_v exp(logits[r,v])
__device__ float         g_adj[R_];            // logcoef - log(rowsum)

// ------------------------- f32 -> bf16 convert -------------------------
__global__ void cvt4_kernel(const float4* __restrict__ in, int which, int n4) {
    __nv_bfloat162* out = (which == 0) ? (__nv_bfloat162*)g_h_bf
                        : (which == 1) ? (__nv_bfloat162*)g_Wlat_bf
                                       : (__nv_bfloat162*)g_Wdec_bf;
    int i = blockIdx.x * blockDim.x + threadIdx.x;
    int stride = gridDim.x * blockDim.x;
    for (; i < n4; i += stride) {
        float4 f = in[i];
        out[2*i+0] = __floats2bfloat162_rn(f.x, f.y);
        out[2*i+1] = __floats2bfloat162_rn(f.z, f.w);
    }
}

// ------------------------- prior: log_coef + rowsum init -------------------------
__global__ void prior_kernel(const float* __restrict__ h,
                             const float* __restrict__ Wp,
                             const float* __restrict__ bp) {
    int l = blockIdx.x;
    int w = threadIdx.x >> 5;   // expert id (4 warps)
    int lane = threadIdx.x & 31;
    const float* hrow = h + (size_t)l * D_;
    float s = 0.f;
    #pragma unroll 4
    for (int i = lane; i < D_; i += 32)
        s += hrow[i] * Wp[i * E_ + w];
    #pragma unroll
    for (int o = 16; o; o >>= 1) s += __shfl_xor_sync(0xffffffffu, s, o);
    __shared__ float sm[E_];
    if (lane == 0) sm[w] = s + bp[w];
    __syncthreads();
    if (threadIdx.x < E_) {
        float m = fmaxf(fmaxf(sm[0], sm[1]), fmaxf(sm[2], sm[3]));
        float sum = expf(sm[0]-m) + expf(sm[1]-m) + expf(sm[2]-m) + expf(sm[3]-m);
        float lse = m + logf(sum);
        g_logcoef[l * E_ + threadIdx.x] = sm[threadIdx.x] - lse;
        g_rowsum[l * E_ + threadIdx.x] = 0.f;   // init for decoder-GEMM atomics
    }
}

// ------------------------- bf16 mma.sync GEMM -------------------------
// C[M,N] = A[M,K] @ B[K,N] (both bf16 row-major), f32 accum.
// EPI 0: latent path  -> tanh(acc + bias[col]) stored bf16 into g_latent (e,d remap)
// EPI 1: decoder path -> acc + bias[col] stored f32 into g_logits, exp-rowsum fused

#define BM 128
#define BN 128
#define BK 32
#define A_STRIDE 56   // bf16 elems per As row (112B: 16B-aligned, LDSM conflict-free)
#define B_STRIDE 136  // bf16 elems per Bs row (272B: 16B-aligned, LDSM conflict-free)

__device__ __forceinline__ uint32_t smem_u32(const void* p) {
    return (uint32_t)__cvta_generic_to_shared(p);
}

template<int EPI, int M, int N, int K>
__global__ __launch_bounds__(256) void gemm_bf16(const float* __restrict__ bias) {
    const __nv_bfloat16* __restrict__ A = (EPI == 0) ? g_h_bf   : g_latent;
    const __nv_bfloat16* __restrict__ B = (EPI == 0) ? g_Wlat_bf : g_Wdec_bf;

    __shared__ __nv_bfloat16 As[BM][A_STRIDE];
    __shared__ __nv_bfloat16 Bs[BK][B_STRIDE];

    const int tid  = threadIdx.x;
    const int warp = tid >> 5;
    const int lane = tid & 31;
    const int wm = warp >> 1;     // 0..3 (M)
    const int wn = warp & 1;      // 0..1 (N)
    const int m0 = blockIdx.y * BM;
    const int n0 = blockIdx.x * BN;

    float acc[2][8][4];
    #pragma unroll
    for (int mi = 0; mi < 2; mi++)
        #pragma unroll
        for (int ni = 0; ni < 8; ni++)
            #pragma unroll
            for (int j = 0; j < 4; j++) acc[mi][ni][j] = 0.f;

    for (int k0 = 0; k0 < K; k0 += BK) {
        // load A tile 128x32 (2 x uint4 per thread)
        #pragma unroll
        for (int i = 0; i < 2; i++) {
            int idx = tid * 2 + i;          // 0..511
            int r = idx >> 2;               // 0..127
            int c = (idx & 3) * 8;          // 0,8,16,24
            *(uint4*)&As[r][c] = *(const uint4*)&A[(size_t)(m0 + r) * K + k0 + c];
        }
        // load B tile 32x128
        #pragma unroll
        for (int i = 0; i < 2; i++) {
            int idx = tid * 2 + i;
            int r = idx >> 4;               // 0..31
            int c = (idx & 15) * 8;
            *(uint4*)&Bs[r][c] = *(const uint4*)&B[(size_t)(k0 + r) * N + n0 + c];
        }
        __syncthreads();

        #pragma unroll
        for (int kk = 0; kk < BK; kk += 16) {
            uint32_t afr[2][4];
            #pragma unroll
            for (int mi = 0; mi < 2; mi++) {
                int row = wm * 32 + mi * 16 + (lane & 15);
                int col = kk + (lane >> 4) * 8;
                uint32_t addr = smem_u32(&As[row][col]);
                asm volatile("ldmatrix.sync.aligned.m8n8.x4.shared.b16 {%0,%1,%2,%3}, [%4];"
                    : "=r"(afr[mi][0]), "=r"(afr[mi][1]), "=r"(afr[mi][2]), "=r"(afr[mi][3])
                    : "r"(addr));
            }
            uint32_t bfr[8][2];
            #pragma unroll
            for (int nj = 0; nj < 4; nj++) {
                int row = kk + (lane & 15);
                int col = wn * 64 + nj * 16 + (lane >> 4) * 8;
                uint32_t addr = smem_u32(&Bs[row][col]);
                asm volatile("ldmatrix.sync.aligned.m8n8.x4.trans.shared.b16 {%0,%1,%2,%3}, [%4];"
                    : "=r"(bfr[nj*2][0]), "=r"(bfr[nj*2][1]),
                      "=r"(bfr[nj*2+1][0]), "=r"(bfr[nj*2+1][1])
                    : "r"(addr));
            }
            #pragma unroll
            for (int mi = 0; mi < 2; mi++)
                #pragma unroll
                for (int ni = 0; ni < 8; ni++) {
                    asm volatile(
                        "mma.sync.aligned.m16n8k16.row.col.f32.bf16.bf16.f32 "
                        "{%0,%1,%2,%3}, {%4,%5,%6,%7}, {%8,%9}, {%0,%1,%2,%3};"
                        : "+f"(acc[mi][ni][0]), "+f"(acc[mi][ni][1]),
                          "+f"(acc[mi][ni][2]), "+f"(acc[mi][ni][3])
                        : "r"(afr[mi][0]), "r"(afr[mi][1]), "r"(afr[mi][2]), "r"(afr[mi][3]),
                          "r"(bfr[ni][0]), "r"(bfr[ni][1]));
                }
        }
        __syncthreads();
    }

    // ---------------- epilogue ----------------
    const int g  = lane >> 2;          // 0..7
    const int c2 = (lane & 3) * 2;     // 0,2,4,6

    if (EPI == 0) {
        #pragma unroll
        for (int mi = 0; mi < 2; mi++)
            #pragma unroll
            for (int ni = 0; ni < 8; ni++) {
                int col = n0 + wn * 64 + ni * 8 + c2;
                int e = col >> 9, d = col & 511;
                float bc0 = bias[col], bc1 = bias[col + 1];
                #pragma unroll
                for (int hh = 0; hh < 2; hh++) {
                    int row = m0 + wm * 32 + mi * 16 + g + hh * 8;   // = l
                    float v0 = tanhf(acc[mi][ni][hh*2+0] + bc0);
                    float v1 = tanhf(acc[mi][ni][hh*2+1] + bc1);
                    *(__nv_bfloat162*)&g_latent[((size_t)row * E_ + e) * D_ + d] =
                        __floats2bfloat162_rn(v0, v1);
                }
            }
    } else {
        float es[2][2] = {{0.f,0.f},{0.f,0.f}};
        #pragma unroll
        for (int mi = 0; mi < 2; mi++)
            #pragma unroll
            for (int ni = 0; ni < 8; ni++) {
                int col = n0 + wn * 64 + ni * 8 + c2;
                float bc0 = bias[col], bc1 = bias[col + 1];
                #pragma unroll
                for (int hh = 0; hh < 2; hh++) {
                    int row = m0 + wm * 32 + mi * 16 + g + hh * 8;
                    float v0 = acc[mi][ni][hh*2+0] + bc0;
                    float v1 = acc[mi][ni][hh*2+1] + bc1;
                    *(float2*)&g_logits[(size_t)row * V_ + col] = make_float2(v0, v1);
                    es[mi][hh] += __expf(v0) + __expf(v1);
                }
            }
        #pragma unroll
        for (int mi = 0; mi < 2; mi++)
            #pragma unroll
            for (int hh = 0; hh < 2; hh++) {
                float s = es[mi][hh];
                s += __shfl_xor_sync(0xffffffffu, s, 1);
                s += __shfl_xor_sync(0xffffffffu, s, 2);
                if ((lane & 3) == 0)
                    atomicAdd(&g_rowsum[m0 + wm * 32 + mi * 16 + g + hh * 8], s);
            }
    }
}

// ------------------------- adj = logcoef - log(rowsum) -------------------------
__global__ void adj_kernel() {
    int r = blockIdx.x * blockDim.x + threadIdx.x;
    if (r < R_) g_adj[r] = g_logcoef[r] - logf(g_rowsum[r]);
}

// ------------------------- combine over experts -------------------------
__global__ void combine_kernel(float* __restrict__ out) {
    int v = blockIdx.x * blockDim.x + threadIdx.x;
    int l = blockIdx.y;
    if (v >= V_) return;
    size_t base = (size_t)l * E_ * V_ + v;
    float a0 = g_logits[base + 0*(size_t)V_] + g_adj[l*E_ + 0];
    float a1 = g_logits[base + 1*(size_t)V_] + g_adj[l*E_ + 1];
    float a2 = g_logits[base + 2*(size_t)V_] + g_adj[l*E_ + 2];
    float a3 = g_logits[base + 3*(size_t)V_] + g_adj[l*E_ + 3];
    float m = fmaxf(fmaxf(a0, a1), fmaxf(a2, a3));
    float s = __expf(a0 - m) + __expf(a1 - m) + __expf(a2 - m) + __expf(a3 - m);
    out[(size_t)l * V_ + v] = m + __logf(s);
}

// ------------------------- launch -------------------------
extern "C" void kernel_launch(void* const* d_in, const int* in_sizes, int n_in,
                              void* d_out, int out_size) {
    const float* h  = (const float*)d_in[0];   // [1,1024,512]
    const float* Wp = (const float*)d_in[1];   // [512,4]
    const float* bp = (const float*)d_in[2];   // [4]
    const float* Wl = (const float*)d_in[3];   // [512,2048]
    const float* bl = (const float*)d_in[4];   // [2048]
    const float* Wd = (const float*)d_in[5];   // [512,32000]
    const float* bd = (const float*)d_in[6];   // [32000]
    float* out = (float*)d_out;                // [1,1024,32000]

    // f32 -> bf16 conversions
    {
        int n4;
        n4 = (L_*D_) / 4;
        cvt4_kernel<<<(n4 + 255) / 256, 256>>>((const float4*)h,  0, n4);
        n4 = (D_*ED_) / 4;
        cvt4_kernel<<<(n4 + 255) / 256, 256>>>((const float4*)Wl, 1, n4);
        n4 = (D_*V_) / 4;
        cvt4_kernel<<<(n4 + 255) / 256, 256>>>((const float4*)Wd, 2, n4);
    }

    // prior logits -> log_coef; zero rowsum
    prior_kernel<<<L_, 128>>>(h, Wp, bp);

    // latent GEMM + tanh  (M=1024, N=2048, K=512)
    {
        dim3 grid(ED_ / BN, L_ / BM);
        gemm_bf16<0, L_, ED_, D_><<<grid, 256>>>(bl);
    }

    // decoder GEMM + exp rowsum  (M=4096, N=32000, K=512)
    {
        dim3 grid(V_ / BN, R_ / BM);
        gemm_bf16<1, R_, V_, D_><<<grid, 256>>>(bd);
    }

    // adj = log_coef - lse
    adj_kernel<<<(R_ + 255) / 256, 256>>>();

    // final combine: out = logsumexp_e(logits + adj)
    {
        dim3 grid(V_ / 256, L_);
        combine_kernel<<<grid, 256>>>(out);
    }
}

// round 3
// speedup vs baseline: 1.4855x; 1.4855x over previous
#include <cuda_runtime.h>
#include <cuda_bf16.h>
#include <math.h>
#include <stdint.h>

#define L_   1024
#define D_   512
#define E_   4
#define V_   32000
#define R_   (L_*E_)     // 4096
#define ED_  (E_*D_)     // 2048

// ------------------------- device scratch -------------------------
__device__ __nv_bfloat16 g_h_bf[L_*D_];
__device__ __nv_bfloat16 g_Wlat_bf[D_*ED_];
__device__ __nv_bfloat16 g_Wdec_bf[(size_t)D_*V_];      // [D, V] row-major bf16
__device__ __nv_bfloat16 g_latent[R_*D_];               // row r = l*4+e
__device__ __nv_bfloat16 g_logits_bf[(size_t)R_*V_];    // 262 MB
__device__ float         g_logcoef[R_];
__device__ float         g_rowsum[R_];
__device__ float         g_adj[R_];

// ------------------------- helpers -------------------------
__device__ __forceinline__ uint32_t smem_u32(const void* p) {
    return (uint32_t)__cvta_generic_to_shared(p);
}
__device__ __forceinline__ void cp_async16(uint32_t dst, const void* src) {
    asm volatile("cp.async.cg.shared.global [%0], [%1], 16;" :: "r"(dst), "l"(src));
}

// ------------------------- f32 -> bf16 convert -------------------------
__global__ void cvt4_kernel(const float4* __restrict__ in, int which, int n4) {
    __nv_bfloat162* out = (which == 0) ? (__nv_bfloat162*)g_h_bf
                        : (which == 1) ? (__nv_bfloat162*)g_Wlat_bf
                                       : (__nv_bfloat162*)g_Wdec_bf;
    int i = blockIdx.x * blockDim.x + threadIdx.x;
    int stride = gridDim.x * blockDim.x;
    for (; i < n4; i += stride) {
        float4 f = in[i];
        out[2*i+0] = __floats2bfloat162_rn(f.x, f.y);
        out[2*i+1] = __floats2bfloat162_rn(f.z, f.w);
    }
}

// ------------------------- prior: log_coef + rowsum init -------------------------
__global__ void prior_kernel(const float* __restrict__ h,
                             const float* __restrict__ Wp,
                             const float* __restrict__ bp) {
    int l = blockIdx.x;
    int w = threadIdx.x >> 5;
    int lane = threadIdx.x & 31;
    const float* hrow = h + (size_t)l * D_;
    float s = 0.f;
    #pragma unroll 4
    for (int i = lane; i < D_; i += 32)
        s += hrow[i] * Wp[i * E_ + w];
    #pragma unroll
    for (int o = 16; o; o >>= 1) s += __shfl_xor_sync(0xffffffffu, s, o);
    __shared__ float sm[E_];
    if (lane == 0) sm[w] = s + bp[w];
    __syncthreads();
    if (threadIdx.x < E_) {
        float m = fmaxf(fmaxf(sm[0], sm[1]), fmaxf(sm[2], sm[3]));
        float sum = expf(sm[0]-m) + expf(sm[1]-m) + expf(sm[2]-m) + expf(sm[3]-m);
        float lse = m + logf(sum);
        g_logcoef[l * E_ + threadIdx.x] = sm[threadIdx.x] - lse;
        g_rowsum[l * E_ + threadIdx.x] = 0.f;
    }
}

// ------------------------- latent GEMM (mma.sync, tanh epilogue) -------------------
#define LBM 128
#define LBN 128
#define LBK 32
#define LA_STRIDE 56
#define LB_STRIDE 136

__global__ __launch_bounds__(256) void latent_gemm(const float* __restrict__ bias) {
    const int K = D_, N = ED_;
    const __nv_bfloat16* __restrict__ A = g_h_bf;
    const __nv_bfloat16* __restrict__ B = g_Wlat_bf;

    __shared__ __nv_bfloat16 As[LBM][LA_STRIDE];
    __shared__ __nv_bfloat16 Bs[LBK][LB_STRIDE];

    const int tid  = threadIdx.x;
    const int warp = tid >> 5;
    const int lane = tid & 31;
    const int wm = warp >> 1, wn = warp & 1;
    const int m0 = blockIdx.y * LBM, n0 = blockIdx.x * LBN;

    float acc[2][8][4];
    #pragma unroll
    for (int mi = 0; mi < 2; mi++)
        #pragma unroll
        for (int ni = 0; ni < 8; ni++)
            #pragma unroll
            for (int j = 0; j < 4; j++) acc[mi][ni][j] = 0.f;

    for (int k0 = 0; k0 < K; k0 += LBK) {
        #pragma unroll
        for (int i = 0; i < 2; i++) {
            int idx = tid * 2 + i;
            int r = idx >> 2, c = (idx & 3) * 8;
            *(uint4*)&As[r][c] = *(const uint4*)&A[(size_t)(m0 + r) * K + k0 + c];
        }
        #pragma unroll
        for (int i = 0; i < 2; i++) {
            int idx = tid * 2 + i;
            int r = idx >> 4, c = (idx & 15) * 8;
            *(uint4*)&Bs[r][c] = *(const uint4*)&B[(size_t)(k0 + r) * N + n0 + c];
        }
        __syncthreads();

        #pragma unroll
        for (int kk = 0; kk < LBK; kk += 16) {
            uint32_t afr[2][4];
            #pragma unroll
            for (int mi = 0; mi < 2; mi++) {
                int row = wm * 32 + mi * 16 + (lane & 15);
                int col = kk + (lane >> 4) * 8;
                uint32_t addr = smem_u32(&As[row][col]);
                asm volatile("ldmatrix.sync.aligned.m8n8.x4.shared.b16 {%0,%1,%2,%3}, [%4];"
                    : "=r"(afr[mi][0]), "=r"(afr[mi][1]), "=r"(afr[mi][2]), "=r"(afr[mi][3])
                    : "r"(addr));
            }
            uint32_t bfr[8][2];
            #pragma unroll
            for (int nj = 0; nj < 4; nj++) {
                int row = kk + (lane & 15);
                int col = wn * 64 + nj * 16 + (lane >> 4) * 8;
                uint32_t addr = smem_u32(&Bs[row][col]);
                asm volatile("ldmatrix.sync.aligned.m8n8.x4.trans.shared.b16 {%0,%1,%2,%3}, [%4];"
                    : "=r"(bfr[nj*2][0]), "=r"(bfr[nj*2][1]),
                      "=r"(bfr[nj*2+1][0]), "=r"(bfr[nj*2+1][1])
                    : "r"(addr));
            }
            #pragma unroll
            for (int mi = 0; mi < 2; mi++)
                #pragma unroll
                for (int ni = 0; ni < 8; ni++) {
                    asm volatile(
                        "mma.sync.aligned.m16n8k16.row.col.f32.bf16.bf16.f32 "
                        "{%0,%1,%2,%3}, {%4,%5,%6,%7}, {%8,%9}, {%0,%1,%2,%3};"
                        : "+f"(acc[mi][ni][0]), "+f"(acc[mi][ni][1]),
                          "+f"(acc[mi][ni][2]), "+f"(acc[mi][ni][3])
                        : "r"(afr[mi][0]), "r"(afr[mi][1]), "r"(afr[mi][2]), "r"(afr[mi][3]),
                          "r"(bfr[ni][0]), "r"(bfr[ni][1]));
                }
        }
        __syncthreads();
    }

    const int g  = lane >> 2;
    const int c2 = (lane & 3) * 2;
    #pragma unroll
    for (int mi = 0; mi < 2; mi++)
        #pragma unroll
        for (int ni = 0; ni < 8; ni++) {
            int col = n0 + wn * 64 + ni * 8 + c2;
            int e = col >> 9, d = col & 511;
            float bc0 = bias[col], bc1 = bias[col + 1];
            #pragma unroll
            for (int hh = 0; hh < 2; hh++) {
                int row = m0 + wm * 32 + mi * 16 + g + hh * 8;
                float v0 = tanhf(acc[mi][ni][hh*2+0] + bc0);
                float v1 = tanhf(acc[mi][ni][hh*2+1] + bc1);
                *(__nv_bfloat162*)&g_latent[((size_t)row * E_ + e) * D_ + d] =
                    __floats2bfloat162_rn(v0, v1);
            }
        }
}

// ------------------------- decoder GEMM: pipelined mma.sync --------------------
// Tile: 256(M) x 128(N) x 32(K), 512 threads (16 warps: 8 M x 2 N), 4-stage cp.async.
#define DBM 256
#define DBN 128
#define DBK 32
#define DA_ROWB 80            // bytes per A smem row (32 bf16 + pad)
#define DB_ROWB 272           // bytes per B smem row (128 bf16 + pad)
#define DA_BYTES (DBM * DA_ROWB)           // 20480
#define DB_BYTES (DBK * DB_ROWB)           // 8704
#define DSTAGE   (DA_BYTES + DB_BYTES)     // 29184
#define DSTAGES  4
#define DEC_SMEM (DSTAGES * DSTAGE)        // 116736

__device__ __forceinline__ void dec_load_stage(uint32_t sbase, int slot,
                                               int m0, int n0, int k0, int tid) {
    uint32_t a_s = sbase + slot * DSTAGE;
    uint32_t b_s = a_s + DA_BYTES;
    #pragma unroll
    for (int i = 0; i < 2; i++) {
        int idx = i * 512 + tid;        // 0..1023
        int r = idx >> 2, p = idx & 3;  // r: 0..255, p: 16B chunk
        cp_async16(a_s + r * DA_ROWB + p * 16,
                   g_latent + (size_t)(m0 + r) * D_ + k0 + p * 8);
    }
    {
        int r = tid >> 4, p = tid & 15; // r: 0..31, p: 0..15
        cp_async16(b_s + r * DB_ROWB + p * 16,
                   g_Wdec_bf + (size_t)(k0 + r) * V_ + n0 + p * 8);
    }
    asm volatile("cp.async.commit_group;" ::: "memory");
}

__global__ void __launch_bounds__(512, 1) dec_gemm(const float* __restrict__ bias) {
    extern __shared__ char dsm[];
    uint32_t sbase = smem_u32(dsm);
    const int tid = threadIdx.x;
    const int warp = tid >> 5, lane = tid & 31;
    const int wm = warp >> 1, wn = warp & 1;       // wm: 0..7, wn: 0..1
    const int n0 = blockIdx.x * DBN, m0 = blockIdx.y * DBM;

    float acc[2][8][4];
    #pragma unroll
    for (int mi = 0; mi < 2; mi++)
        #pragma unroll
        for (int ni = 0; ni < 8; ni++)
            #pragma unroll
            for (int j = 0; j < 4; j++) acc[mi][ni][j] = 0.f;

    // prefetch 3 stages
    dec_load_stage(sbase, 0, m0, n0, 0,  tid);
    dec_load_stage(sbase, 1, m0, n0, 32, tid);
    dec_load_stage(sbase, 2, m0, n0, 64, tid);

    #pragma unroll
    for (int it = 0; it < 16; it++) {
        if (it < 14)      asm volatile("cp.async.wait_group 2;" ::: "memory");
        else if (it == 14) asm volatile("cp.async.wait_group 1;" ::: "memory");
        else               asm volatile("cp.async.wait_group 0;" ::: "memory");
        __syncthreads();
        if (it + 3 < 16)
            dec_load_stage(sbase, (it + 3) & 3, m0, n0, (it + 3) * 32, tid);

        uint32_t a_s = sbase + (it & 3) * DSTAGE;
        uint32_t b_s = a_s + DA_BYTES;

        #pragma unroll
        for (int kk = 0; kk < DBK; kk += 16) {
            uint32_t afr[2][4];
            #pragma unroll
            for (int mi = 0; mi < 2; mi++) {
                int row = wm * 32 + mi * 16 + (lane & 15);
                int colb = (kk + (lane >> 4) * 8) * 2;
                uint32_t addr = a_s + row * DA_ROWB + colb;
                asm volatile("ldmatrix.sync.aligned.m8n8.x4.shared.b16 {%0,%1,%2,%3}, [%4];"
                    : "=r"(afr[mi][0]), "=r"(afr[mi][1]), "=r"(afr[mi][2]), "=r"(afr[mi][3])
                    : "r"(addr));
            }
            uint32_t bfr[8][2];
            #pragma unroll
            for (int nj = 0; nj < 4; nj++) {
                int row = kk + (lane & 15);
                int colb = (wn * 64 + nj * 16 + (lane >> 4) * 8) * 2;
                uint32_t addr = b_s + row * DB_ROWB + colb;
                asm volatile("ldmatrix.sync.aligned.m8n8.x4.trans.shared.b16 {%0,%1,%2,%3}, [%4];"
                    : "=r"(bfr[nj*2][0]), "=r"(bfr[nj*2][1]),
                      "=r"(bfr[nj*2+1][0]), "=r"(bfr[nj*2+1][1])
                    : "r"(addr));
            }
            #pragma unroll
            for (int mi = 0; mi < 2; mi++)
                #pragma unroll
                for (int ni = 0; ni < 8; ni++) {
                    asm volatile(
                        "mma.sync.aligned.m16n8k16.row.col.f32.bf16.bf16.f32 "
                        "{%0,%1,%2,%3}, {%4,%5,%6,%7}, {%8,%9}, {%0,%1,%2,%3};"
                        : "+f"(acc[mi][ni][0]), "+f"(acc[mi][ni][1]),
                          "+f"(acc[mi][ni][2]), "+f"(acc[mi][ni][3])
                        : "r"(afr[mi][0]), "r"(afr[mi][1]), "r"(afr[mi][2]), "r"(afr[mi][3]),
                          "r"(bfr[ni][0]), "r"(bfr[ni][1]));
                }
        }
    }

    // -------- epilogue: bias add, bf16 store, fused exp-rowsum --------
    const int g  = lane >> 2;
    const int c2 = (lane & 3) * 2;
    float es[2][2] = {{0.f, 0.f}, {0.f, 0.f}};
    #pragma unroll
    for (int mi = 0; mi < 2; mi++)
        #pragma unroll
        for (int ni = 0; ni < 8; ni++) {
            int col = n0 + wn * 64 + ni * 8 + c2;
            float bc0 = bias[col], bc1 = bias[col + 1];
            #pragma unroll
            for (int hh = 0; hh < 2; hh++) {
                int row = m0 + wm * 32 + mi * 16 + g + hh * 8;
                float v0 = acc[mi][ni][hh*2+0] + bc0;
                float v1 = acc[mi][ni][hh*2+1] + bc1;
                es[mi][hh] += __expf(v0) + __expf(v1);
                *(__nv_bfloat162*)&g_logits_bf[(size_t)row * V_ + col] =
                    __floats2bfloat162_rn(v0, v1);
            }
        }
    #pragma unroll
    for (int mi = 0; mi < 2; mi++)
        #pragma unroll
        for (int hh = 0; hh < 2; hh++) {
            float s = es[mi][hh];
            s += __shfl_xor_sync(0xffffffffu, s, 1);
            s += __shfl_xor_sync(0xffffffffu, s, 2);
            if ((lane & 3) == 0)
                atomicAdd(&g_rowsum[m0 + wm * 32 + mi * 16 + g + hh * 8], s);
        }
}

// ------------------------- adj = logcoef - log(rowsum) -------------------------
__global__ void adj_kernel() {
    int r = blockIdx.x * blockDim.x + threadIdx.x;
    if (r < R_) g_adj[r] = g_logcoef[r] - logf(g_rowsum[r]);
}

// ------------------------- combine over experts -------------------------
__global__ void combine_kernel(float* __restrict__ out) {
    int l = blockIdx.y;
    int v0 = (blockIdx.x * blockDim.x + threadIdx.x) * 8;
    if (v0 >= V_) return;
    float adj[4];
    #pragma unroll
    for (int e = 0; e < 4; e++) adj[e] = g_adj[4 * l + e];
    float a[4][8];
    #pragma unroll
    for (int e = 0; e < 4; e++) {
        uint4 q = *(const uint4*)&g_logits_bf[((size_t)(4 * l + e)) * V_ + v0];
        const __nv_bfloat162* h2 = (const __nv_bfloat162*)&q;
        #pragma unroll
        for (int p = 0; p < 4; p++) {
            float2 f = __bfloat1622float2(h2[p]);
            a[e][2*p]   = f.x + adj[e];
            a[e][2*p+1] = f.y + adj[e];
        }
    }
    float res[8];
    #pragma unroll
    for (int j = 0; j < 8; j++) {
        float m = fmaxf(fmaxf(a[0][j], a[1][j]), fmaxf(a[2][j], a[3][j]));
        float s = __expf(a[0][j]-m) + __expf(a[1][j]-m) + __expf(a[2][j]-m) + __expf(a[3][j]-m);
        res[j] = m + __logf(s);
    }
    *(float4*)&out[(size_t)l * V_ + v0]     = *(float4*)&res[0];
    *(float4*)&out[(size_t)l * V_ + v0 + 4] = *(float4*)&res[4];
}

// ------------------------- launch -------------------------
extern "C" void kernel_launch(void* const* d_in, const int* in_sizes, int n_in,
                              void* d_out, int out_size) {
    const float* h  = (const float*)d_in[0];
    const float* Wp = (const float*)d_in[1];
    const float* bp = (const float*)d_in[2];
    const float* Wl = (const float*)d_in[3];
    const float* bl = (const float*)d_in[4];
    const float* Wd = (const float*)d_in[5];
    const float* bd = (const float*)d_in[6];
    float* out = (float*)d_out;

    cudaFuncSetAttribute(dec_gemm, cudaFuncAttributeMaxDynamicSharedMemorySize, DEC_SMEM);

    {
        int n4 = (L_*D_) / 4;
        cvt4_kernel<<<(n4 + 255) / 256, 256>>>((const float4*)h, 0, n4);
        n4 = (D_*ED_) / 4;
        cvt4_kernel<<<(n4 + 255) / 256, 256>>>((const float4*)Wl, 1, n4);
        n4 = (D_*V_) / 4;
        cvt4_kernel<<<(n4 + 255) / 256, 256>>>((const float4*)Wd, 2, n4);
    }

    prior_kernel<<<L_, 128>>>(h, Wp, bp);

    {
        dim3 grid(ED_ / LBN, L_ / LBM);
        latent_gemm<<<grid, 256>>>(bl);
    }

    {
        dim3 grid(V_ / DBN, R_ / DBM);
        dec_gemm<<<grid, 512, DEC_SMEM>>>(bd);
    }

    adj_kernel<<<(R_ + 255) / 256, 256>>>();

    {
        dim3 grid((V_ / 8 + 255) / 256, L_);
        combine_kernel<<<grid, 256>>>(out);
    }
}

// round 5
// speedup vs baseline: 1.5587x; 1.0493x over previous
#include <cuda_runtime.h>
#include <cuda_bf16.h>
#include <math.h>
#include <stdint.h>

#define L_   1024
#define D_   512
#define E_   4
#define V_   32000
#define R_   (L_*E_)     // 4096
#define ED_  (E_*D_)     // 2048

// ------------------------- device scratch -------------------------
__device__ __nv_bfloat16 g_h_bf[L_*D_];
__device__ __nv_bfloat16 g_Wlat_bf[D_*ED_];
__device__ __nv_bfloat16 g_Wdec_bf[(size_t)D_*V_];      // [D, V] row-major bf16
__device__ __nv_bfloat16 g_latent[R_*D_];               // row r = l*4+e
__device__ __nv_bfloat16 g_logits_bf[(size_t)R_*V_];    // 262 MB
__device__ float         g_logcoef[R_];
__device__ float         g_rowsum[R_];

// ------------------------- helpers -------------------------
__device__ __forceinline__ uint32_t smem_u32(const void* p) {
    return (uint32_t)__cvta_generic_to_shared(p);
}
__device__ __forceinline__ void cp_async16(uint32_t dst, const void* src) {
    asm volatile("cp.async.cg.shared.global [%0], [%1], 16;" :: "r"(dst), "l"(src));
}

// ------------------------- all converts + rowsum zero, one launch ------------------
__global__ void cvt_all_kernel(const float4* __restrict__ h,
                               const float4* __restrict__ Wl,
                               const float4* __restrict__ Wd) {
    const int stride = gridDim.x * blockDim.x;
    int t = blockIdx.x * blockDim.x + threadIdx.x;
    // h: 131072 f32 = 32768 float4
    for (int i = t; i < (L_*D_)/4; i += stride) {
        float4 f = h[i];
        ((__nv_bfloat162*)g_h_bf)[2*i+0] = __floats2bfloat162_rn(f.x, f.y);
        ((__nv_bfloat162*)g_h_bf)[2*i+1] = __floats2bfloat162_rn(f.z, f.w);
    }
    // Wl: 1M f32 = 262144 float4
    for (int i = t; i < (D_*ED_)/4; i += stride) {
        float4 f = Wl[i];
        ((__nv_bfloat162*)g_Wlat_bf)[2*i+0] = __floats2bfloat162_rn(f.x, f.y);
        ((__nv_bfloat162*)g_Wlat_bf)[2*i+1] = __floats2bfloat162_rn(f.z, f.w);
    }
    // Wd: 16.384M f32 = 4.096M float4
    for (int i = t; i < (D_*V_)/4; i += stride) {
        float4 f = Wd[i];
        ((__nv_bfloat162*)g_Wdec_bf)[2*i+0] = __floats2bfloat162_rn(f.x, f.y);
        ((__nv_bfloat162*)g_Wdec_bf)[2*i+1] = __floats2bfloat162_rn(f.z, f.w);
    }
    if (t < R_) g_rowsum[t] = 0.f;
}

// ------------------------- prior: log_coef -------------------------
__global__ void prior_kernel(const float* __restrict__ h,
                             const float* __restrict__ Wp,
                             const float* __restrict__ bp) {
    int l = blockIdx.x;
    int w = threadIdx.x >> 5;
    int lane = threadIdx.x & 31;
    const float* hrow = h + (size_t)l * D_;
    float s = 0.f;
    #pragma unroll 4
    for (int i = lane; i < D_; i += 32)
        s += hrow[i] * Wp[i * E_ + w];
    #pragma unroll
    for (int o = 16; o; o >>= 1) s += __shfl_xor_sync(0xffffffffu, s, o);
    __shared__ float sm[E_];
    if (lane == 0) sm[w] = s + bp[w];
    __syncthreads();
    if (threadIdx.x < E_) {
        float m = fmaxf(fmaxf(sm[0], sm[1]), fmaxf(sm[2], sm[3]));
        float sum = expf(sm[0]-m) + expf(sm[1]-m) + expf(sm[2]-m) + expf(sm[3]-m);
        float lse = m + logf(sum);
        g_logcoef[l * E_ + threadIdx.x] = sm[threadIdx.x] - lse;
    }
}

// ------------------------- latent GEMM (mma.sync, tanh epilogue) -------------------
#define LBM 128
#define LBN 128
#define LBK 32
#define LA_STRIDE 56
#define LB_STRIDE 136

__global__ __launch_bounds__(256) void latent_gemm(const float* __restrict__ bias) {
    const int K = D_, N = ED_;
    const __nv_bfloat16* __restrict__ A = g_h_bf;
    const __nv_bfloat16* __restrict__ B = g_Wlat_bf;

    __shared__ __nv_bfloat16 As[LBM][LA_STRIDE];
    __shared__ __nv_bfloat16 Bs[LBK][LB_STRIDE];

    const int tid  = threadIdx.x;
    const int warp = tid >> 5;
    const int lane = tid & 31;
    const int wm = warp >> 1, wn = warp & 1;
    const int m0 = blockIdx.y * LBM, n0 = blockIdx.x * LBN;

    float acc[2][8][4];
    #pragma unroll
    for (int mi = 0; mi < 2; mi++)
        #pragma unroll
        for (int ni = 0; ni < 8; ni++)
            #pragma unroll
            for (int j = 0; j < 4; j++) acc[mi][ni][j] = 0.f;

    for (int k0 = 0; k0 < K; k0 += LBK) {
        #pragma unroll
        for (int i = 0; i < 2; i++) {
            int idx = tid * 2 + i;
            int r = idx >> 2, c = (idx & 3) * 8;
            *(uint4*)&As[r][c] = *(const uint4*)&A[(size_t)(m0 + r) * K + k0 + c];
        }
        #pragma unroll
        for (int i = 0; i < 2; i++) {
            int idx = tid * 2 + i;
            int r = idx >> 4, c = (idx & 15) * 8;
            *(uint4*)&Bs[r][c] = *(const uint4*)&B[(size_t)(k0 + r) * N + n0 + c];
        }
        __syncthreads();

        #pragma unroll
        for (int kk = 0; kk < LBK; kk += 16) {
            uint32_t afr[2][4];
            #pragma unroll
            for (int mi = 0; mi < 2; mi++) {
                int row = wm * 32 + mi * 16 + (lane & 15);
                int col = kk + (lane >> 4) * 8;
                uint32_t addr = smem_u32(&As[row][col]);
                asm volatile("ldmatrix.sync.aligned.m8n8.x4.shared.b16 {%0,%1,%2,%3}, [%4];"
                    : "=r"(afr[mi][0]), "=r"(afr[mi][1]), "=r"(afr[mi][2]), "=r"(afr[mi][3])
                    : "r"(addr));
            }
            uint32_t bfr[8][2];
            #pragma unroll
            for (int nj = 0; nj < 4; nj++) {
                int row = kk + (lane & 15);
                int col = wn * 64 + nj * 16 + (lane >> 4) * 8;
                uint32_t addr = smem_u32(&Bs[row][col]);
                asm volatile("ldmatrix.sync.aligned.m8n8.x4.trans.shared.b16 {%0,%1,%2,%3}, [%4];"
                    : "=r"(bfr[nj*2][0]), "=r"(bfr[nj*2][1]),
                      "=r"(bfr[nj*2+1][0]), "=r"(bfr[nj*2+1][1])
                    : "r"(addr));
            }
            #pragma unroll
            for (int mi = 0; mi < 2; mi++)
                #pragma unroll
                for (int ni = 0; ni < 8; ni++) {
                    asm volatile(
                        "mma.sync.aligned.m16n8k16.row.col.f32.bf16.bf16.f32 "
                        "{%0,%1,%2,%3}, {%4,%5,%6,%7}, {%8,%9}, {%0,%1,%2,%3};"
                        : "+f"(acc[mi][ni][0]), "+f"(acc[mi][ni][1]),
                          "+f"(acc[mi][ni][2]), "+f"(acc[mi][ni][3])
                        : "r"(afr[mi][0]), "r"(afr[mi][1]), "r"(afr[mi][2]), "r"(afr[mi][3]),
                          "r"(bfr[ni][0]), "r"(bfr[ni][1]));
                }
        }
        __syncthreads();
    }

    const int g  = lane >> 2;
    const int c2 = (lane & 3) * 2;
    #pragma unroll
    for (int mi = 0; mi < 2; mi++)
        #pragma unroll
        for (int ni = 0; ni < 8; ni++) {
            int col = n0 + wn * 64 + ni * 8 + c2;
            int e = col >> 9, d = col & 511;
            float bc0 = bias[col], bc1 = bias[col + 1];
            #pragma unroll
            for (int hh = 0; hh < 2; hh++) {
                int row = m0 + wm * 32 + mi * 16 + g + hh * 8;
                float v0 = tanhf(acc[mi][ni][hh*2+0] + bc0);
                float v1 = tanhf(acc[mi][ni][hh*2+1] + bc1);
                *(__nv_bfloat162*)&g_latent[((size_t)row * E_ + e) * D_ + d] =
                    __floats2bfloat162_rn(v0, v1);
            }
        }
}

// ------------------------- decoder GEMM: pipelined mma.sync --------------------
#define DBM 256
#define DBN 128
#define DBK 32
#define DA_ROWB 80
#define DB_ROWB 272
#define DA_BYTES (DBM * DA_ROWB)           // 20480
#define DB_BYTES (DBK * DB_ROWB)           // 8704
#define DSTAGE   (DA_BYTES + DB_BYTES)     // 29184
#define DSTAGES  4
#define DEC_SMEM (DSTAGES * DSTAGE)        // 116736
#define EPI_ROWB 272                       // epilogue staging stride (bank-safe)

__device__ __forceinline__ void dec_load_stage(uint32_t sbase, int slot,
                                               int m0, int n0, int k0, int tid) {
    uint32_t a_s = sbase + slot * DSTAGE;
    uint32_t b_s = a_s + DA_BYTES;
    #pragma unroll
    for (int i = 0; i < 2; i++) {
        int idx = i * 512 + tid;
        int r = idx >> 2, p = idx & 3;
        cp_async16(a_s + r * DA_ROWB + p * 16,
                   g_latent + (size_t)(m0 + r) * D_ + k0 + p * 8);
    }
    {
        int r = tid >> 4, p = tid & 15;
        cp_async16(b_s + r * DB_ROWB + p * 16,
                   g_Wdec_bf + (size_t)(k0 + r) * V_ + n0 + p * 8);
    }
    asm volatile("cp.async.commit_group;" ::: "memory");
}

__global__ void __launch_bounds__(512, 1) dec_gemm(const float* __restrict__ bias) {
    extern __shared__ char dsm[];
    uint32_t sbase = smem_u32(dsm);
    const int tid = threadIdx.x;
    const int warp = tid >> 5, lane = tid & 31;
    const int wm = warp >> 1, wn = warp & 1;
    const int n0 = blockIdx.x * DBN, m0 = blockIdx.y * DBM;

    float acc[2][8][4];
    #pragma unroll
    for (int mi = 0; mi < 2; mi++)
        #pragma unroll
        for (int ni = 0; ni < 8; ni++)
            #pragma unroll
            for (int j = 0; j < 4; j++) acc[mi][ni][j] = 0.f;

    dec_load_stage(sbase, 0, m0, n0, 0,  tid);
    dec_load_stage(sbase, 1, m0, n0, 32, tid);
    dec_load_stage(sbase, 2, m0, n0, 64, tid);

    #pragma unroll
    for (int it = 0; it < 16; it++) {
        if (it < 14)       asm volatile("cp.async.wait_group 2;" ::: "memory");
        else if (it == 14) asm volatile("cp.async.wait_group 1;" ::: "memory");
        else               asm volatile("cp.async.wait_group 0;" ::: "memory");
        __syncthreads();
        if (it + 3 < 16)
            dec_load_stage(sbase, (it + 3) & 3, m0, n0, (it + 3) * 32, tid);

        uint32_t a_s = sbase + (it & 3) * DSTAGE;
        uint32_t b_s = a_s + DA_BYTES;

        #pragma unroll
        for (int kk = 0; kk < DBK; kk += 16) {
            uint32_t afr[2][4];
            #pragma unroll
            for (int mi = 0; mi < 2; mi++) {
                int row = wm * 32 + mi * 16 + (lane & 15);
                int colb = (kk + (lane >> 4) * 8) * 2;
                uint32_t addr = a_s + row * DA_ROWB + colb;
                asm volatile("ldmatrix.sync.aligned.m8n8.x4.shared.b16 {%0,%1,%2,%3}, [%4];"
                    : "=r"(afr[mi][0]), "=r"(afr[mi][1]), "=r"(afr[mi][2]), "=r"(afr[mi][3])
                    : "r"(addr));
            }
            uint32_t bfr[8][2];
            #pragma unroll
            for (int nj = 0; nj < 4; nj++) {
                int row = kk + (lane & 15);
                int colb = (wn * 64 + nj * 16 + (lane >> 4) * 8) * 2;
                uint32_t addr = b_s + row * DB_ROWB + colb;
                asm volatile("ldmatrix.sync.aligned.m8n8.x4.trans.shared.b16 {%0,%1,%2,%3}, [%4];"
                    : "=r"(bfr[nj*2][0]), "=r"(bfr[nj*2][1]),
                      "=r"(bfr[nj*2+1][0]), "=r"(bfr[nj*2+1][1])
                    : "r"(addr));
            }
            #pragma unroll
            for (int mi = 0; mi < 2; mi++)
                #pragma unroll
                for (int ni = 0; ni < 8; ni++) {
                    asm volatile(
                        "mma.sync.aligned.m16n8k16.row.col.f32.bf16.bf16.f32 "
                        "{%0,%1,%2,%3}, {%4,%5,%6,%7}, {%8,%9}, {%0,%1,%2,%3};"
                        : "+f"(acc[mi][ni][0]), "+f"(acc[mi][ni][1]),
                          "+f"(acc[mi][ni][2]), "+f"(acc[mi][ni][3])
                        : "r"(afr[mi][0]), "r"(afr[mi][1]), "r"(afr[mi][2]), "r"(afr[mi][3]),
                          "r"(bfr[ni][0]), "r"(bfr[ni][1]));
                }
        }
    }

    // -------- epilogue: bias add + exp-rowsum, stage bf16 in smem, coalesced STG ----
    __syncthreads();   // mainloop smem dead -> reuse as staging
    const int g  = lane >> 2;
    const int c2 = (lane & 3) * 2;
    float es[2][2] = {{0.f, 0.f}, {0.f, 0.f}};
    #pragma unroll
    for (int mi = 0; mi < 2; mi++)
        #pragma unroll
        for (int ni = 0; ni < 8; ni++) {
            int col = wn * 64 + ni * 8 + c2;
            float bc0 = bias[n0 + col], bc1 = bias[n0 + col + 1];
            #pragma unroll
            for (int hh = 0; hh < 2; hh++) {
                int row = wm * 32 + mi * 16 + g + hh * 8;
                float v0 = acc[mi][ni][hh*2+0] + bc0;
                float v1 = acc[mi][ni][hh*2+1] + bc1;
                es[mi][hh] += __expf(v0) + __expf(v1);
                __nv_bfloat162 t2 = __floats2bfloat162_rn(v0, v1);
                asm volatile("st.shared.b32 [%0], %1;"
                    :: "r"(sbase + row * EPI_ROWB + col * 2), "r"(*(uint32_t*)&t2));
            }
        }
    #pragma unroll
    for (int mi = 0; mi < 2; mi++)
        #pragma unroll
        for (int hh = 0; hh < 2; hh++) {
            float s = es[mi][hh];
            s += __shfl_xor_sync(0xffffffffu, s, 1);
            s += __shfl_xor_sync(0xffffffffu, s, 2);
            if ((lane & 3) == 0)
                atomicAdd(&g_rowsum[m0 + wm * 32 + mi * 16 + g + hh * 8], s);
        }
    __syncthreads();
    // coalesced copy smem -> gmem: 4096 uint4 chunks, 8 per thread
    #pragma unroll
    for (int i = 0; i < 8; i++) {
        int chunk = i * 512 + tid;
        int r = chunk >> 4, c = chunk & 15;
        uint4 q;
        asm volatile("ld.shared.v4.b32 {%0,%1,%2,%3}, [%4];"
            : "=r"(q.x), "=r"(q.y), "=r"(q.z), "=r"(q.w)
            : "r"(sbase + r * EPI_ROWB + c * 16));
        *(uint4*)&g_logits_bf[(size_t)(m0 + r) * V_ + n0 + c * 8] = q;
    }
}

// ------------------------- combine (adj fused) -------------------------
__global__ void combine_kernel(float* __restrict__ out) {
    int l = blockIdx.y;
    __shared__ float sadj[E_];
    if (threadIdx.x < E_)
        sadj[threadIdx.x] = g_logcoef[4*l + threadIdx.x] - logf(g_rowsum[4*l + threadIdx.x]);
    __syncthreads();
    int v0 = (blockIdx.x * blockDim.x + threadIdx.x) * 8;
    if (v0 >= V_) return;
    float adj[4];
    #pragma unroll
    for (int e = 0; e < 4; e++) adj[e] = sadj[e];
    float a[4][8];
    #pragma unroll
    for (int e = 0; e < 4; e++) {
        uint4 q = *(const uint4*)&g_logits_bf[((size_t)(4 * l + e)) * V_ + v0];
        const __nv_bfloat162* h2 = (const __nv_bfloat162*)&q;
        #pragma unroll
        for (int p = 0; p < 4; p++) {
            float2 f = __bfloat1622float2(h2[p]);
            a[e][2*p]   = f.x + adj[e];
            a[e][2*p+1] = f.y + adj[e];
        }
    }
    float res[8];
    #pragma unroll
    for (int j = 0; j < 8; j++) {
        float m = fmaxf(fmaxf(a[0][j], a[1][j]), fmaxf(a[2][j], a[3][j]));
        float s = __expf(a[0][j]-m) + __expf(a[1][j]-m) + __expf(a[2][j]-m) + __expf(a[3][j]-m);
        res[j] = m + __logf(s);
    }
    *(float4*)&out[(size_t)l * V_ + v0]     = *(float4*)&res[0];
    *(float4*)&out[(size_t)l * V_ + v0 + 4] = *(float4*)&res[4];
}

// ------------------------- launch -------------------------
extern "C" void kernel_launch(void* const* d_in, const int* in_sizes, int n_in,
                              void* d_out, int out_size) {
    const float* h  = (const float*)d_in[0];
    const float* Wp = (const float*)d_in[1];
    const float* bp = (const float*)d_in[2];
    const float* Wl = (const float*)d_in[3];
    const float* bl = (const float*)d_in[4];
    const float* Wd = (const float*)d_in[5];
    const float* bd = (const float*)d_in[6];
    float* out = (float*)d_out;

    cudaFuncSetAttribute(dec_gemm, cudaFuncAttributeMaxDynamicSharedMemorySize, DEC_SMEM);

    // launch 0: all converts + rowsum zero
    cvt_all_kernel<<<592, 256>>>((const float4*)h, (const float4*)Wl, (const float4*)Wd);

    // launch 1: latent GEMM
    {
        dim3 grid(ED_ / LBN, L_ / LBM);
        latent_gemm<<<grid, 256>>>(bl);
    }

    // launch 2: prior (only needed before combine)
    prior_kernel<<<L_, 128>>>(h, Wp, bp);

    // launch 3: decoder GEMM  (target of ncu capture slot)
    {
        dim3 grid(V_ / DBN, R_ / DBM);
        dec_gemm<<<grid, 512, DEC_SMEM>>>(bd);
    }

    // launch 4: combine (adj fused)
    {
        dim3 grid((V_ / 8 + 255) / 256, L_);
        combine_kernel<<<grid, 256>>>(out);
    }
}

// round 6
// speedup vs baseline: 1.7073x; 1.0953x over previous
#include <cuda_runtime.h>
#include <cuda_bf16.h>
#include <math.h>
#include <stdint.h>

#define L_   1024
#define D_   512
#define E_   4
#define V_   32000
#define R_   (L_*E_)     // 4096
#define ED_  (E_*D_)     // 2048

// ------------------------- device scratch -------------------------
__device__ __nv_bfloat16 g_h_bf[L_*D_];
__device__ __nv_bfloat16 g_Wlat_bf[D_*ED_];
__device__ __nv_bfloat16 g_Wdec_bf[(size_t)D_*V_];      // [D, V] row-major bf16
__device__ __nv_bfloat16 g_latent[R_*D_];               // row r = l*4+e
__device__ __nv_bfloat16 g_logits_bf[(size_t)R_*V_];    // 262 MB
__device__ float         g_logcoef[R_];
__device__ float         g_rowsum[R_];

// ------------------------- helpers -------------------------
__device__ __forceinline__ uint32_t smem_u32(const void* p) {
    return (uint32_t)__cvta_generic_to_shared(p);
}
__device__ __forceinline__ void cp_async16(uint32_t dst, const void* src) {
    asm volatile("cp.async.cg.shared.global [%0], [%1], 16;" :: "r"(dst), "l"(src));
}

// ------------------------- all converts + rowsum zero, one launch ------------------
__global__ void cvt_all_kernel(const float4* __restrict__ h,
                               const float4* __restrict__ Wl,
                               const float4* __restrict__ Wd) {
    const int stride = gridDim.x * blockDim.x;
    int t = blockIdx.x * blockDim.x + threadIdx.x;
    for (int i = t; i < (L_*D_)/4; i += stride) {
        float4 f = h[i];
        ((__nv_bfloat162*)g_h_bf)[2*i+0] = __floats2bfloat162_rn(f.x, f.y);
        ((__nv_bfloat162*)g_h_bf)[2*i+1] = __floats2bfloat162_rn(f.z, f.w);
    }
    for (int i = t; i < (D_*ED_)/4; i += stride) {
        float4 f = Wl[i];
        ((__nv_bfloat162*)g_Wlat_bf)[2*i+0] = __floats2bfloat162_rn(f.x, f.y);
        ((__nv_bfloat162*)g_Wlat_bf)[2*i+1] = __floats2bfloat162_rn(f.z, f.w);
    }
    for (int i = t; i < (D_*V_)/4; i += stride) {
        float4 f = Wd[i];
        ((__nv_bfloat162*)g_Wdec_bf)[2*i+0] = __floats2bfloat162_rn(f.x, f.y);
        ((__nv_bfloat162*)g_Wdec_bf)[2*i+1] = __floats2bfloat162_rn(f.z, f.w);
    }
    if (t < R_) g_rowsum[t] = 0.f;
}

// ------------------------- prior: log_coef -------------------------
__global__ void prior_kernel(const float* __restrict__ h,
                             const float* __restrict__ Wp,
                             const float* __restrict__ bp) {
    int l = blockIdx.x;
    int w = threadIdx.x >> 5;
    int lane = threadIdx.x & 31;
    const float* hrow = h + (size_t)l * D_;
    float s = 0.f;
    #pragma unroll 4
    for (int i = lane; i < D_; i += 32)
        s += hrow[i] * Wp[i * E_ + w];
    #pragma unroll
    for (int o = 16; o; o >>= 1) s += __shfl_xor_sync(0xffffffffu, s, o);
    __shared__ float sm[E_];
    if (lane == 0) sm[w] = s + bp[w];
    __syncthreads();
    if (threadIdx.x < E_) {
        float m = fmaxf(fmaxf(sm[0], sm[1]), fmaxf(sm[2], sm[3]));
        float sum = expf(sm[0]-m) + expf(sm[1]-m) + expf(sm[2]-m) + expf(sm[3]-m);
        float lse = m + logf(sum);
        g_logcoef[l * E_ + threadIdx.x] = sm[threadIdx.x] - lse;
    }
}

// ------------------------- latent GEMM (mma.sync, tanh epilogue) -------------------
#define LBM 128
#define LBN 128
#define LBK 32
#define LA_STRIDE 56
#define LB_STRIDE 136

__global__ __launch_bounds__(256) void latent_gemm(const float* __restrict__ bias) {
    const int K = D_, N = ED_;
    const __nv_bfloat16* __restrict__ A = g_h_bf;
    const __nv_bfloat16* __restrict__ B = g_Wlat_bf;

    __shared__ __nv_bfloat16 As[LBM][LA_STRIDE];
    __shared__ __nv_bfloat16 Bs[LBK][LB_STRIDE];

    const int tid  = threadIdx.x;
    const int warp = tid >> 5;
    const int lane = tid & 31;
    const int wm = warp >> 1, wn = warp & 1;
    const int m0 = blockIdx.y * LBM, n0 = blockIdx.x * LBN;

    float acc[2][8][4];
    #pragma unroll
    for (int mi = 0; mi < 2; mi++)
        #pragma unroll
        for (int ni = 0; ni < 8; ni++)
            #pragma unroll
            for (int j = 0; j < 4; j++) acc[mi][ni][j] = 0.f;

    for (int k0 = 0; k0 < K; k0 += LBK) {
        #pragma unroll
        for (int i = 0; i < 2; i++) {
            int idx = tid * 2 + i;
            int r = idx >> 2, c = (idx & 3) * 8;
            *(uint4*)&As[r][c] = *(const uint4*)&A[(size_t)(m0 + r) * K + k0 + c];
        }
        #pragma unroll
        for (int i = 0; i < 2; i++) {
            int idx = tid * 2 + i;
            int r = idx >> 4, c = (idx & 15) * 8;
            *(uint4*)&Bs[r][c] = *(const uint4*)&B[(size_t)(k0 + r) * N + n0 + c];
        }
        __syncthreads();

        #pragma unroll
        for (int kk = 0; kk < LBK; kk += 16) {
            uint32_t afr[2][4];
            #pragma unroll
            for (int mi = 0; mi < 2; mi++) {
                int row = wm * 32 + mi * 16 + (lane & 15);
                int col = kk + (lane >> 4) * 8;
                uint32_t addr = smem_u32(&As[row][col]);
                asm volatile("ldmatrix.sync.aligned.m8n8.x4.shared.b16 {%0,%1,%2,%3}, [%4];"
                    : "=r"(afr[mi][0]), "=r"(afr[mi][1]), "=r"(afr[mi][2]), "=r"(afr[mi][3])
                    : "r"(addr));
            }
            uint32_t bfr[8][2];
            #pragma unroll
            for (int nj = 0; nj < 4; nj++) {
                int row = kk + (lane & 15);
                int col = wn * 64 + nj * 16 + (lane >> 4) * 8;
                uint32_t addr = smem_u32(&Bs[row][col]);
                asm volatile("ldmatrix.sync.aligned.m8n8.x4.trans.shared.b16 {%0,%1,%2,%3}, [%4];"
                    : "=r"(bfr[nj*2][0]), "=r"(bfr[nj*2][1]),
                      "=r"(bfr[nj*2+1][0]), "=r"(bfr[nj*2+1][1])
                    : "r"(addr));
            }
            #pragma unroll
            for (int mi = 0; mi < 2; mi++)
                #pragma unroll
                for (int ni = 0; ni < 8; ni++) {
                    asm volatile(
                        "mma.sync.aligned.m16n8k16.row.col.f32.bf16.bf16.f32 "
                        "{%0,%1,%2,%3}, {%4,%5,%6,%7}, {%8,%9}, {%0,%1,%2,%3};"
                        : "+f"(acc[mi][ni][0]), "+f"(acc[mi][ni][1]),
                          "+f"(acc[mi][ni][2]), "+f"(acc[mi][ni][3])
                        : "r"(afr[mi][0]), "r"(afr[mi][1]), "r"(afr[mi][2]), "r"(afr[mi][3]),
                          "r"(bfr[ni][0]), "r"(bfr[ni][1]));
                }
        }
        __syncthreads();
    }

    const int g  = lane >> 2;
    const int c2 = (lane & 3) * 2;
    #pragma unroll
    for (int mi = 0; mi < 2; mi++)
        #pragma unroll
        for (int ni = 0; ni < 8; ni++) {
            int col = n0 + wn * 64 + ni * 8 + c2;
            int e = col >> 9, d = col & 511;
            float bc0 = bias[col], bc1 = bias[col + 1];
            #pragma unroll
            for (int hh = 0; hh < 2; hh++) {
                int row = m0 + wm * 32 + mi * 16 + g + hh * 8;
                float v0 = tanhf(acc[mi][ni][hh*2+0] + bc0);
                float v1 = tanhf(acc[mi][ni][hh*2+1] + bc1);
                *(__nv_bfloat162*)&g_latent[((size_t)row * E_ + e) * D_ + d] =
                    __floats2bfloat162_rn(v0, v1);
            }
        }
}

// ------------------------- decoder GEMM: pipelined mma.sync, 2 CTA/SM ----------
#define DBM 128
#define DBN 128
#define DBK 32
#define DA_ROWB 80
#define DB_ROWB 272
#define DA_BYTES (DBM * DA_ROWB)           // 10240
#define DB_BYTES (DBK * DB_ROWB)           // 8704
#define DSTAGE   (DA_BYTES + DB_BYTES)     // 18944
#define DSTAGES  4
#define DEC_SMEM (DSTAGES * DSTAGE)        // 75776
#define EPI_ROWB 272

__device__ __forceinline__ void dec_load_stage(uint32_t sbase, int slot,
                                               int m0, int n0, int k0, int tid) {
    uint32_t a_s = sbase + slot * DSTAGE;
    uint32_t b_s = a_s + DA_BYTES;
    #pragma unroll
    for (int i = 0; i < 2; i++) {
        int idx = i * 256 + tid;        // 0..511
        int r = idx >> 2, p = idx & 3;  // r: 0..127
        cp_async16(a_s + r * DA_ROWB + p * 16,
                   g_latent + (size_t)(m0 + r) * D_ + k0 + p * 8);
    }
    #pragma unroll
    for (int i = 0; i < 2; i++) {
        int idx = i * 256 + tid;        // 0..511
        int r = idx >> 4, p = idx & 15; // r: 0..31
        cp_async16(b_s + r * DB_ROWB + p * 16,
                   g_Wdec_bf + (size_t)(k0 + r) * V_ + n0 + p * 8);
    }
    asm volatile("cp.async.commit_group;" ::: "memory");
}

__global__ void __launch_bounds__(256, 2) dec_gemm(const float* __restrict__ bias) {
    extern __shared__ char dsm[];
    uint32_t sbase = smem_u32(dsm);
    const int tid = threadIdx.x;
    const int warp = tid >> 5, lane = tid & 31;
    const int wm = warp >> 1, wn = warp & 1;       // wm: 0..3, wn: 0..1
    const int n0 = blockIdx.x * DBN, m0 = blockIdx.y * DBM;

    float acc[2][8][4];
    #pragma unroll
    for (int mi = 0; mi < 2; mi++)
        #pragma unroll
        for (int ni = 0; ni < 8; ni++)
            #pragma unroll
            for (int j = 0; j < 4; j++) acc[mi][ni][j] = 0.f;

    dec_load_stage(sbase, 0, m0, n0, 0,  tid);
    dec_load_stage(sbase, 1, m0, n0, 32, tid);
    dec_load_stage(sbase, 2, m0, n0, 64, tid);

    #pragma unroll
    for (int it = 0; it < 16; it++) {
        if (it < 14)       asm volatile("cp.async.wait_group 2;" ::: "memory");
        else if (it == 14) asm volatile("cp.async.wait_group 1;" ::: "memory");
        else               asm volatile("cp.async.wait_group 0;" ::: "memory");
        __syncthreads();
        if (it + 3 < 16)
            dec_load_stage(sbase, (it + 3) & 3, m0, n0, (it + 3) * 32, tid);

        uint32_t a_s = sbase + (it & 3) * DSTAGE;
        uint32_t b_s = a_s + DA_BYTES;

        #pragma unroll
        for (int kk = 0; kk < DBK; kk += 16) {
            uint32_t afr[2][4];
            #pragma unroll
            for (int mi = 0; mi < 2; mi++) {
                int row = wm * 32 + mi * 16 + (lane & 15);
                int colb = (kk + (lane >> 4) * 8) * 2;
                uint32_t addr = a_s + row * DA_ROWB + colb;
                asm volatile("ldmatrix.sync.aligned.m8n8.x4.shared.b16 {%0,%1,%2,%3}, [%4];"
                    : "=r"(afr[mi][0]), "=r"(afr[mi][1]), "=r"(afr[mi][2]), "=r"(afr[mi][3])
                    : "r"(addr));
            }
            uint32_t bfr[8][2];
            #pragma unroll
            for (int nj = 0; nj < 4; nj++) {
                int row = kk + (lane & 15);
                int colb = (wn * 64 + nj * 16 + (lane >> 4) * 8) * 2;
                uint32_t addr = b_s + row * DB_ROWB + colb;
                asm volatile("ldmatrix.sync.aligned.m8n8.x4.trans.shared.b16 {%0,%1,%2,%3}, [%4];"
                    : "=r"(bfr[nj*2][0]), "=r"(bfr[nj*2][1]),
                      "=r"(bfr[nj*2+1][0]), "=r"(bfr[nj*2+1][1])
                    : "r"(addr));
            }
            #pragma unroll
            for (int mi = 0; mi < 2; mi++)
                #pragma unroll
                for (int ni = 0; ni < 8; ni++) {
                    asm volatile(
                        "mma.sync.aligned.m16n8k16.row.col.f32.bf16.bf16.f32 "
                        "{%0,%1,%2,%3}, {%4,%5,%6,%7}, {%8,%9}, {%0,%1,%2,%3};"
                        : "+f"(acc[mi][ni][0]), "+f"(acc[mi][ni][1]),
                          "+f"(acc[mi][ni][2]), "+f"(acc[mi][ni][3])
                        : "r"(afr[mi][0]), "r"(afr[mi][1]), "r"(afr[mi][2]), "r"(afr[mi][3]),
                          "r"(bfr[ni][0]), "r"(bfr[ni][1]));
                }
        }
    }

    // -------- epilogue: bias add + exp-rowsum, stage bf16 in smem, coalesced STG ----
    __syncthreads();
    const int g  = lane >> 2;
    const int c2 = (lane & 3) * 2;
    float es[2][2] = {{0.f, 0.f}, {0.f, 0.f}};
    #pragma unroll
    for (int mi = 0; mi < 2; mi++)
        #pragma unroll
        for (int ni = 0; ni < 8; ni++) {
            int col = wn * 64 + ni * 8 + c2;
            float bc0 = bias[n0 + col], bc1 = bias[n0 + col + 1];
            #pragma unroll
            for (int hh = 0; hh < 2; hh++) {
                int row = wm * 32 + mi * 16 + g + hh * 8;
                float v0 = acc[mi][ni][hh*2+0] + bc0;
                float v1 = acc[mi][ni][hh*2+1] + bc1;
                es[mi][hh] += __expf(v0) + __expf(v1);
                __nv_bfloat162 t2 = __floats2bfloat162_rn(v0, v1);
                asm volatile("st.shared.b32 [%0], %1;"
                    :: "r"(sbase + row * EPI_ROWB + col * 2), "r"(*(uint32_t*)&t2));
            }
        }
    #pragma unroll
    for (int mi = 0; mi < 2; mi++)
        #pragma unroll
        for (int hh = 0; hh < 2; hh++) {
            float s = es[mi][hh];
            s += __shfl_xor_sync(0xffffffffu, s, 1);
            s += __shfl_xor_sync(0xffffffffu, s, 2);
            if ((lane & 3) == 0)
                atomicAdd(&g_rowsum[m0 + wm * 32 + mi * 16 + g + hh * 8], s);
        }
    __syncthreads();
    // coalesced copy smem -> gmem: 2048 uint4 chunks, 8 per thread
    #pragma unroll
    for (int i = 0; i < 8; i++) {
        int chunk = i * 256 + tid;
        int r = chunk >> 4, c = chunk & 15;
        uint4 q;
        asm volatile("ld.shared.v4.b32 {%0,%1,%2,%3}, [%4];"
            : "=r"(q.x), "=r"(q.y), "=r"(q.z), "=r"(q.w)
            : "r"(sbase + r * EPI_ROWB + c * 16));
        *(uint4*)&g_logits_bf[(size_t)(m0 + r) * V_ + n0 + c * 8] = q;
    }
}

// ------------------------- combine (adj fused) -------------------------
__global__ void combine_kernel(float* __restrict__ out) {
    int l = blockIdx.y;
    __shared__ float sadj[E_];
    if (threadIdx.x < E_)
        sadj[threadIdx.x] = g_logcoef[4*l + threadIdx.x] - logf(g_rowsum[4*l + threadIdx.x]);
    __syncthreads();
    int v0 = (blockIdx.x * blockDim.x + threadIdx.x) * 8;
    if (v0 >= V_) return;
    float adj[4];
    #pragma unroll
    for (int e = 0; e < 4; e++) adj[e] = sadj[e];
    float a[4][8];
    #pragma unroll
    for (int e = 0; e < 4; e++) {
        uint4 q = *(const uint4*)&g_logits_bf[((size_t)(4 * l + e)) * V_ + v0];
        const __nv_bfloat162* h2 = (const __nv_bfloat162*)&q;
        #pragma unroll
        for (int p = 0; p < 4; p++) {
            float2 f = __bfloat1622float2(h2[p]);
            a[e][2*p]   = f.x + adj[e];
            a[e][2*p+1] = f.y + adj[e];
        }
    }
    float res[8];
    #pragma unroll
    for (int j = 0; j < 8; j++) {
        float m = fmaxf(fmaxf(a[0][j], a[1][j]), fmaxf(a[2][j], a[3][j]));
        float s = __expf(a[0][j]-m) + __expf(a[1][j]-m) + __expf(a[2][j]-m) + __expf(a[3][j]-m);
        res[j] = m + __logf(s);
    }
    *(float4*)&out[(size_t)l * V_ + v0]     = *(float4*)&res[0];
    *(float4*)&out[(size_t)l * V_ + v0 + 4] = *(float4*)&res[4];
}

// ------------------------- launch -------------------------
extern "C" void kernel_launch(void* const* d_in, const int* in_sizes, int n_in,
                              void* d_out, int out_size) {
    const float* h  = (const float*)d_in[0];
    const float* Wp = (const float*)d_in[1];
    const float* bp = (const float*)d_in[2];
    const float* Wl = (const float*)d_in[3];
    const float* bl = (const float*)d_in[4];
    const float* Wd = (const float*)d_in[5];
    const float* bd = (const float*)d_in[6];
    float* out = (float*)d_out;

    cudaFuncSetAttribute(dec_gemm, cudaFuncAttributeMaxDynamicSharedMemorySize, DEC_SMEM);

    // launch 0: all converts + rowsum zero
    cvt_all_kernel<<<592, 256>>>((const float4*)h, (const float4*)Wl, (const float4*)Wd);

    // launch 1: latent GEMM
    {
        dim3 grid(ED_ / LBN, L_ / LBM);
        latent_gemm<<<grid, 256>>>(bl);
    }

    // launch 2: prior
    prior_kernel<<<L_, 128>>>(h, Wp, bp);

    // launch 3: decoder GEMM (ncu capture slot)
    {
        dim3 grid(V_ / DBN, R_ / DBM);
        dec_gemm<<<grid, 256, DEC_SMEM>>>(bd);
    }

    // launch 4: combine
    {
        dim3 grid((V_ / 8 + 255) / 256, L_);
        combine_kernel<<<grid, 256>>>(out);
    }
}